// round 16
// baseline (speedup 1.0000x reference)
#include <cuda_runtime.h>
#include <cstdint>

#define NCB   9
#define DIN   512
#define TLEN  4096
#define BATCH 16
#define KCB   1024
#define DCB   8

#define CODES_N   (BATCH * NCB * TLEN)          // 589824
#define LATENT_N  (BATCH * DIN * TLEN)          // 33554432
#define LOSS_OFF  (CODES_N + LATENT_N)
#define LOSS_DEN  (1.0f / (float)(BATCH * DCB * TLEN))   // exact pow2

#define TOKC 64      // tokens per CTA (32 pairs); 512 threads, warp owns 2 pairs

// ---- blob sizes (floats) ----
#define BLOBA_F 4144      // Win scalar [8][516] = 4128 + bin 16
#define BLOBB_F 14848     // CBN [1024][10] 10240 | WOUT_T [8][512] 4096 | BOUT 512
#define BLOBA_BYTES (BLOBA_F * 4)   // 16576
#define BLOBB_BYTES (BLOBB_F * 4)   // 59392

// ---- smem float offsets (16B-aligned) ----
#define F_R2    0         // 32 pairs * 514 u64 = 32896 floats
#define F_A0    32896     // 4144
#define F_A1    37040     // 4144
#define F_B     41184     // 14848
#define F_MB    56032     // two u64 mbarriers
#define F_TOT   56040     // 224160 bytes

// float offsets inside B
#define F_CBN   F_B                    // [k][10]
#define F_WOUTT (F_B + 10240)
#define F_BOUTX (F_B + 14336)

// ---------------- device scratch: per-stage weight blobs ----------------
__device__ __align__(16) float g_blobA[NCB * BLOBA_F];
__device__ __align__(16) float g_blobB[NCB * BLOBB_F];

typedef unsigned long long u64;

// ---------------- packed fp32x2 helpers ----------------
__device__ __forceinline__ u64 pk2(float a, float b) {
    u64 r; asm("mov.b64 %0,{%1,%2};" : "=l"(r) : "f"(a), "f"(b)); return r;
}
__device__ __forceinline__ u64 dup2(float a) {
    u64 r; asm("mov.b64 %0,{%1,%1};" : "=l"(r) : "f"(a)); return r;
}
__device__ __forceinline__ void up2(u64 v, float& a, float& b) {
    asm("mov.b64 {%0,%1},%2;" : "=f"(a), "=f"(b) : "l"(v));
}
__device__ __forceinline__ u64 f2(u64 a, u64 b, u64 c) {
    u64 d; asm("fma.rn.f32x2 %0,%1,%2,%3;" : "=l"(d) : "l"(a), "l"(b), "l"(c)); return d;
}
__device__ __forceinline__ u64 a2(u64 a, u64 b) {
    u64 d; asm("add.rn.f32x2 %0,%1,%2;" : "=l"(d) : "l"(a), "l"(b)); return d;
}
__device__ __forceinline__ u64 s2(u64 a, u64 b) {   // a - b (exact IEEE)
    return a2(a, b ^ 0x8000000080000000ULL);
}

// NEON VF4+FMA sum of squares over 8 values (reference reduce ordering)
__device__ __forceinline__ float ssq8_neon(const float* x) {
    float p0 = __fmaf_rn(x[4], x[4], __fmul_rn(x[0], x[0]));
    float p1 = __fmaf_rn(x[5], x[5], __fmul_rn(x[1], x[1]));
    float p2 = __fmaf_rn(x[6], x[6], __fmul_rn(x[2], x[2]));
    float p3 = __fmaf_rn(x[7], x[7], __fmul_rn(x[3], x[3]));
    return __fadd_rn(__fadd_rn(p0, p1), __fadd_rn(p2, p3));
}

// ---------------- mbarrier + bulk copy helpers ----------------
__device__ __forceinline__ void mbar_init(uint32_t mbar, uint32_t cnt) {
    asm volatile("mbarrier.init.shared.b64 [%0], %1;" :: "r"(mbar), "r"(cnt) : "memory");
}
__device__ __forceinline__ void mbar_expect(uint32_t mbar, uint32_t bytes) {
    asm volatile("mbarrier.arrive.expect_tx.shared.b64 _, [%0], %1;"
                 :: "r"(mbar), "r"(bytes) : "memory");
}
__device__ __forceinline__ void mbar_wait(uint32_t mbar, uint32_t parity) {
    asm volatile(
        "{\n\t.reg .pred P;\n"
        "W_%=:\n\t"
        "mbarrier.try_wait.parity.shared.b64 P, [%0], %1;\n\t"
        "@P bra D_%=;\n\t"
        "bra W_%=;\n"
        "D_%=:\n\t}"
        :: "r"(mbar), "r"(parity) : "memory");
}
__device__ __forceinline__ void bulk_cp(uint32_t dst, const void* src,
                                        uint32_t bytes, uint32_t mbar) {
    asm volatile(
        "cp.async.bulk.shared::cluster.global.mbarrier::complete_tx::bytes "
        "[%0], [%1], %2, [%3];"
        :: "r"(dst), "l"(src), "r"(bytes), "r"(mbar) : "memory");
}

// ---------------- init ----------------
__global__ void rvq_init(float* out) {
    if (threadIdx.x < 2) out[LOSS_OFF + threadIdx.x] = 0.0f;
}

// ---------------- prep: bake stage blobs (FP orderings identical to R12) --------
__global__ void rvq_prep(const float* __restrict__ in_v, const float* __restrict__ in_g,
                         const float* __restrict__ in_b,
                         const float* __restrict__ out_v, const float* __restrict__ out_g,
                         const float* __restrict__ out_b,
                         const float* __restrict__ cbs) {
    const int cb  = blockIdx.x;
    const int tid = threadIdx.x;
    float* bA = g_blobA + cb * BLOBA_F;
    float* bB = g_blobB + cb * BLOBB_F;

    // W_in [8,512]: thread per row; norm = VF4xIC2 FMA accumulators + faddp tree.
    if (tid < DCB) {
        const float* v = in_v + (cb * DCB + tid) * DIN;
        float a[8];
        #pragma unroll
        for (int j = 0; j < 8; j++) a[j] = 0.f;
        for (int k = 0; k < DIN / 8; k++) {
            #pragma unroll
            for (int j = 0; j < 8; j++) {
                float x = v[8 * k + j];
                a[j] = __fmaf_rn(x, x, a[j]);
            }
        }
        float b0 = __fadd_rn(a[0], a[4]);
        float b1 = __fadd_rn(a[1], a[5]);
        float b2 = __fadd_rn(a[2], a[6]);
        float b3 = __fadd_rn(a[3], a[7]);
        float ss = __fadd_rn(__fadd_rn(b0, b1), __fadd_rn(b2, b3));
        float nrm = __fsqrt_rn(ss);
        float g   = in_g[cb * DCB + tid];
        float* dst = bA + tid * 516;
        for (int c = 0; c < DIN; c++) dst[c] = __fdiv_rn(__fmul_rn(g, v[c]), nrm);
        dst[512] = 0.f; dst[513] = 0.f; dst[514] = 0.f; dst[515] = 0.f;
    }
    if (tid < 16) bA[4128 + tid] = (tid < 8) ? in_b[cb * DCB + tid] : 0.f;

    // W_out [512,8]: 8-norm via NEON VF4; TRANSPOSED scalar store [d][c].
    for (int i = tid; i < DIN; i += blockDim.x) {
        const float* v = out_v + (cb * DIN + i) * DCB;
        float vv[8];
        #pragma unroll
        for (int d = 0; d < DCB; d++) vv[d] = v[d];
        float nrm = __fsqrt_rn(ssq8_neon(vv));
        float g   = out_g[cb * DIN + i];
        #pragma unroll
        for (int d = 0; d < DCB; d++)
            bB[10240 + d * 512 + i] = __fdiv_rn(__fmul_rn(g, vv[d]), nrm);
        bB[14336 + i] = out_b[cb * DIN + i];
    }
    // codebook rows: [k][10] = {cb_n[0..7], cn2, 0}; sums via NEON VF4.
    for (int k = tid; k < KCB; k += blockDim.x) {
        const float* v = cbs + (cb * KCB + k) * DCB;
        float vv[8];
        #pragma unroll
        for (int d = 0; d < DCB; d++) vv[d] = v[d];
        float denom = fmaxf(__fsqrt_rn(ssq8_neon(vv)), 1e-12f);
        float cn[8];
        #pragma unroll
        for (int d = 0; d < DCB; d++) {
            cn[d] = __fdiv_rn(vv[d], denom);
            bB[k * 10 + d] = cn[d];
        }
        bB[k * 10 + 8] = ssq8_neon(cn);
        bB[k * 10 + 9] = 0.f;
    }
}

// ---------------- main fused kernel ----------------
// 512 threads = 16 warps; warp w owns pairs 2w, 2w+1 (tokens 4w..4w+3).
// All phases warp-local; ONE CTA barrier per stage (weight buffer guard).
__global__ void __launch_bounds__(512, 1)
rvq_main(const float* __restrict__ z, const float* __restrict__ cbs,
         float* __restrict__ out) {
    extern __shared__ float smF[];
    u64* smU = (u64*)smF;
    uint32_t smB;
    asm("{.reg .u64 t; cvta.to.shared.u64 t, %1; cvt.u32.u64 %0, t;}"
        : "=r"(smB) : "l"(smF));
    const uint32_t mbA = smB + F_MB * 4u;
    const uint32_t mbBr = smB + F_MB * 4u + 8u;

    const int tid  = threadIdx.x;
    const int lane = tid & 31;
    const int w    = tid >> 5;

    const int tokCTA = blockIdx.x * TOKC;
    const int b     = tokCTA >> 12;
    const int tbase = tokCTA & 4095;

    if (tid == 0) { mbar_init(mbA, 1); mbar_init(mbBr, 1); }

    // ---- load z into R2[p][c] = (z[2p][c], z[2p+1][c]) ----
    {
        const int p = tid & 31, c0 = tid >> 5;   // c0 in [0,16)
        const float* zp = z + ((size_t)b << 21) + tbase + 2 * p;
        u64* rb = smU + (size_t)p * 514;
        #pragma unroll 4
        for (int it = 0; it < 32; it++) {
            int c = c0 + 16 * it;
            float2 v = *(const float2*)(zp + ((size_t)c << 12));
            rb[c] = pk2(v.x, v.y);
        }
    }
    __syncthreads();   // mbar init + R2 visible
    if (tid == 0) {    // prefetch A(0)
        mbar_expect(mbA, BLOBA_BYTES);
        bulk_cp(smB + F_A0 * 4u, g_blobA, BLOBA_BYTES, mbA);
    }

    u64 lossG[2] = {0ULL, 0ULL};

    for (int cb = 0; cb < NCB; cb++) {
        // stage top (post end-of-stage barrier): B(cb) copy
        if (tid == 0) {
            mbar_expect(mbBr, BLOBB_BYTES);
            bulk_cp(smB + F_B * 4u, g_blobB + cb * BLOBB_F, BLOBB_BYTES, mbBr);
        }
        mbar_wait(mbA, cb & 1);   // A(cb) ready (phase flipped)
        // A(cb+1) prefetch AFTER the wait — phase has flipped, expect opens next phase
        if (tid == 0 && cb + 1 < NCB) {
            mbar_expect(mbA, BLOBA_BYTES);
            bulk_cp(smB + (uint32_t)((cb & 1) ? F_A0 : F_A1) * 4u,
                    g_blobA + (cb + 1) * BLOBA_F, BLOBA_BYTES, mbA);
        }
        const float* aCur = smF + ((cb & 1) ? F_A1 : F_A0);

        // ---- phase 1 (warp-local, lanes 0-15): sequential ascending FMA chain ----
        u64 ze2 = 0ULL;
        if (lane < 16) {
            const int pl = lane >> 3, oo = lane & 7;
            const float4* wrow = (const float4*)(aCur + oo * 516);
            const u64* rr = smU + (2 * w + pl) * 514;
            u64 acc = 0ULL;
            #pragma unroll 8
            for (int c4 = 0; c4 < 128; c4++) {
                float4 wv = wrow[c4];
                ulonglong2 r01 = *(const ulonglong2*)(rr + 4 * c4);
                ulonglong2 r23 = *(const ulonglong2*)(rr + 4 * c4 + 2);
                acc = f2(dup2(wv.x), r01.x, acc);
                acc = f2(dup2(wv.y), r01.y, acc);
                acc = f2(dup2(wv.z), r23.x, acc);
                acc = f2(dup2(wv.w), r23.y, acc);
            }
            ze2 = a2(acc, dup2(aCur[4128 + oo]));
        }

        // ---- gather ze for this warp's 2 pairs via shuffles ----
        u64 zep[2][8];
        #pragma unroll
        for (int g = 0; g < 2; g++)
            #pragma unroll
            for (int o = 0; o < 8; o++)
                zep[g][o] = __shfl_sync(0xffffffffu, ze2, g * 8 + o);

        // ---- normalization (NEON ordering per token) ----
        u64 zen[2][8], seG[2];
        #pragma unroll
        for (int g = 0; g < 2; g++) {
            float lo[8], hi[8];
            #pragma unroll
            for (int o = 0; o < 8; o++) up2(zep[g][o], lo[o], hi[o]);
            float dl = fmaxf(__fsqrt_rn(ssq8_neon(lo)), 1e-12f);
            float dh = fmaxf(__fsqrt_rn(ssq8_neon(hi)), 1e-12f);
            float nl[8], nh[8];
            #pragma unroll
            for (int o = 0; o < 8; o++) {
                nl[o] = __fdiv_rn(lo[o], dl);
                nh[o] = __fdiv_rn(hi[o], dh);
                zen[g][o] = pk2(nl[o], nh[o]);
            }
            seG[g] = pk2(ssq8_neon(nl), ssq8_neon(nh));
        }
        const u64 NEG2 = dup2(-2.0f);

        mbar_wait(mbBr, cb & 1);  // B(cb) ready

        // ---- phase 2: dist = (s_e - 2*dot) + c_k ; argmin over 1024 ----
        float bestv[4];
        int   besti[4];
        #pragma unroll
        for (int j = 0; j < 4; j++) { bestv[j] = 3.4e38f; besti[j] = 0; }
        #pragma unroll 2
        for (int kk = 0; kk < 32; kk++) {
            int k = (kk << 5) + lane;
            const float* cbrow = smF + F_CBN + k * 10;
            float2 c01 = *(const float2*)(cbrow);
            float2 c23 = *(const float2*)(cbrow + 2);
            float2 c45 = *(const float2*)(cbrow + 4);
            float2 c67 = *(const float2*)(cbrow + 6);
            float cw[8] = {c01.x, c01.y, c23.x, c23.y, c45.x, c45.y, c67.x, c67.y};
            float cn2k = cbrow[8];
            u64 d0 = 0ULL, d1 = 0ULL;
            #pragma unroll
            for (int d = 0; d < 8; d++) {       // sequential ascending FMA (Eigen k=8)
                u64 wc = dup2(cw[d]);
                d0 = f2(wc, zen[0][d], d0);
                d1 = f2(wc, zen[1][d], d1);
            }
            u64 c2p = dup2(cn2k);
            u64 s0 = a2(f2(d0, NEG2, seG[0]), c2p);
            u64 s1 = a2(f2(d1, NEG2, seG[1]), c2p);
            float f[4];
            up2(s0, f[0], f[1]); up2(s1, f[2], f[3]);
            #pragma unroll
            for (int j = 0; j < 4; j++)
                if (f[j] < bestv[j]) { bestv[j] = f[j]; besti[j] = k; }
        }
        // cross-lane argmin, first-index tie-break
        #pragma unroll
        for (int j = 0; j < 4; j++) {
            #pragma unroll
            for (int s = 16; s > 0; s >>= 1) {
                float ov = __shfl_xor_sync(0xffffffffu, bestv[j], s);
                int   oi = __shfl_xor_sync(0xffffffffu, besti[j], s);
                if (ov < bestv[j] || (ov == bestv[j] && oi < besti[j])) {
                    bestv[j] = ov; besti[j] = oi;
                }
            }
        }

        // codes output (float), layout [B][NCB][T]; warp tokens = tbase+4w..+3
        {
            float* cOut = out + (((size_t)(b * NCB + cb)) << 12) + tbase + 4 * w;
            int myi = besti[0];
            if (lane == 1) myi = besti[1];
            if (lane == 2) myi = besti[2];
            if (lane == 3) myi = besti[3];
            if (lane < 4) cOut[lane] = (float)myi;
        }

        // losses + straight-through qst (registers; warp-uniform values)
        u64 qst[2][8];
        #pragma unroll
        for (int g = 0; g < 2; g++) {
            const float* qlo = cbs + ((size_t)(cb * KCB + besti[2 * g]) << 3);
            const float* qhi = cbs + ((size_t)(cb * KCB + besti[2 * g + 1]) << 3);
            #pragma unroll
            for (int d = 0; d < 8; d++) {
                u64 zq = pk2(__ldg(qlo + d), __ldg(qhi + d));
                u64 ze = zep[g][d];
                u64 e  = s2(ze, zq);
                lossG[g] = f2(e, e, lossG[g]);
                qst[g][d] = a2(ze, s2(zq, ze));   // z_e + (z_q - z_e)
            }
        }

        // ---- phase 3 (warp-local): residual[own 2 pairs] -= (W_out @ qst + b_out) ----
        {
            #pragma unroll 2
            for (int c16 = 0; c16 < 16; c16++) {
                const int c = lane + 32 * c16;
                u64 Wd[8];
                #pragma unroll
                for (int d = 0; d < 8; d++)
                    Wd[d] = dup2(smF[F_WOUTT + d * 512 + c]);
                const u64 bc = dup2(smF[F_BOUTX + c]);
                #pragma unroll
                for (int g = 0; g < 2; g++) {
                    u64 acc = 0ULL;
                    #pragma unroll
                    for (int d = 0; d < 8; d++) acc = f2(Wd[d], qst[g][d], acc);
                    acc = a2(acc, bc);
                    u64* rp = smU + (2 * w + g) * 514 + c;
                    *rp = s2(*rp, acc);
                }
            }
        }
        __syncthreads();   // end of stage: weight buffers reusable next stage
    }

    // ---- epilogue: latent = z - residual_final ----
    {
        const int p = tid & 31, c0 = tid >> 5;
        const float* zp = z + ((size_t)b << 21) + tbase + 2 * p;
        float* lp = out + CODES_N + ((size_t)b << 21) + tbase + 2 * p;
        const u64* rb = smU + (size_t)p * 514;
        #pragma unroll 4
        for (int it = 0; it < 32; it++) {
            int c = c0 + 16 * it;
            float2 zv = *(const float2*)(zp + ((size_t)c << 12));
            float rl, rh;
            up2(rb[c], rl, rh);
            float2 lv;
            lv.x = __fadd_rn(zv.x, -rl);
            lv.y = __fadd_rn(zv.y, -rh);
            *(float2*)(lp + ((size_t)c << 12)) = lv;
        }
    }
    if (lane == 0) {
        float t0, t1, acc = 0.f;
        #pragma unroll
        for (int g = 0; g < 2; g++) {
            up2(lossG[g], t0, t1);
            acc = __fadd_rn(acc, __fadd_rn(t0, t1));
        }
        float wl = __fmul_rn(acc, LOSS_DEN);
        atomicAdd(out + LOSS_OFF, wl);       // closs
        atomicAdd(out + LOSS_OFF + 1, wl);   // bloss (== closs exactly)
    }
}

extern "C" void kernel_launch(void* const* d_in, const int* in_sizes, int n_in,
                              void* d_out, int out_size) {
    const float* z     = (const float*)d_in[0];
    const float* in_v  = (const float*)d_in[1];
    const float* in_g  = (const float*)d_in[2];
    const float* in_b  = (const float*)d_in[3];
    const float* out_v = (const float*)d_in[4];
    const float* out_g = (const float*)d_in[5];
    const float* out_b = (const float*)d_in[6];
    const float* cbs   = (const float*)d_in[7];
    float* out = (float*)d_out;

    cudaFuncSetAttribute(rvq_main, cudaFuncAttributeMaxDynamicSharedMemorySize,
                         F_TOT * sizeof(float));

    rvq_init<<<1, 32>>>(out);
    rvq_prep<<<NCB, 256>>>(in_v, in_g, in_b, out_v, out_g, out_b, cbs);
    rvq_main<<<(BATCH * TLEN) / TOKC, 512, F_TOT * sizeof(float)>>>(z, cbs, out);
}

// round 17
// speedup vs baseline: 1.0785x; 1.0785x over previous
#include <cuda_runtime.h>
#include <cstdint>

#define NCB   9
#define DIN   512
#define TLEN  4096
#define BATCH 16
#define KCB   1024
#define DCB   8

#define CODES_N   (BATCH * NCB * TLEN)          // 589824
#define LATENT_N  (BATCH * DIN * TLEN)          // 33554432
#define LOSS_OFF  (CODES_N + LATENT_N)
#define LOSS_DEN  (1.0f / (float)(BATCH * DCB * TLEN))   // exact pow2

#define TOKC 64      // tokens per CTA (32 pairs); 8 compute warps + 1 producer warp

// ---- blob sizes (floats) ----
#define BLOBA_F 4144      // Win scalar [8][516] = 4128 + bin 16
#define BLOBB_F 14848     // CBN [1024][10] 10240 | WOUT_T [8][512] 4096 | BOUT 512
#define BLOBA_BYTES (BLOBA_F * 4)   // 16576
#define BLOBB_BYTES (BLOBB_F * 4)   // 59392

// ---- smem float offsets (16B-aligned) ----
#define F_R2    0         // 32 pairs * 514 u64 = 32896 floats
#define F_A0    32896     // 4144
#define F_A1    37040     // 4144
#define F_B     41184     // 14848
#define F_MB    56032     // 6 u64 mbarriers = 12 floats
#define F_TOT   56048     // 224192 bytes

// float offsets inside B
#define F_CBN   F_B                    // [k][10]
#define F_WOUTT (F_B + 10240)
#define F_BOUTX (F_B + 14336)

// mbarrier byte offsets from smem base
#define MB_AR0  (F_MB * 4 + 0)
#define MB_AR1  (F_MB * 4 + 8)
#define MB_BR   (F_MB * 4 + 16)
#define MB_AF0  (F_MB * 4 + 24)
#define MB_AF1  (F_MB * 4 + 32)
#define MB_BF   (F_MB * 4 + 40)

// ---------------- device scratch: per-stage weight blobs ----------------
__device__ __align__(16) float g_blobA[NCB * BLOBA_F];
__device__ __align__(16) float g_blobB[NCB * BLOBB_F];

typedef unsigned long long u64;

// ---------------- packed fp32x2 helpers ----------------
__device__ __forceinline__ u64 pk2(float a, float b) {
    u64 r; asm("mov.b64 %0,{%1,%2};" : "=l"(r) : "f"(a), "f"(b)); return r;
}
__device__ __forceinline__ u64 dup2(float a) {
    u64 r; asm("mov.b64 %0,{%1,%1};" : "=l"(r) : "f"(a)); return r;
}
__device__ __forceinline__ void up2(u64 v, float& a, float& b) {
    asm("mov.b64 {%0,%1},%2;" : "=f"(a), "=f"(b) : "l"(v));
}
__device__ __forceinline__ u64 f2(u64 a, u64 b, u64 c) {
    u64 d; asm("fma.rn.f32x2 %0,%1,%2,%3;" : "=l"(d) : "l"(a), "l"(b), "l"(c)); return d;
}
__device__ __forceinline__ u64 a2(u64 a, u64 b) {
    u64 d; asm("add.rn.f32x2 %0,%1,%2;" : "=l"(d) : "l"(a), "l"(b)); return d;
}
__device__ __forceinline__ u64 s2(u64 a, u64 b) {   // a - b (exact IEEE)
    return a2(a, b ^ 0x8000000080000000ULL);
}

// NEON VF4+FMA sum of squares over 8 values (reference reduce ordering)
__device__ __forceinline__ float ssq8_neon(const float* x) {
    float p0 = __fmaf_rn(x[4], x[4], __fmul_rn(x[0], x[0]));
    float p1 = __fmaf_rn(x[5], x[5], __fmul_rn(x[1], x[1]));
    float p2 = __fmaf_rn(x[6], x[6], __fmul_rn(x[2], x[2]));
    float p3 = __fmaf_rn(x[7], x[7], __fmul_rn(x[3], x[3]));
    return __fadd_rn(__fadd_rn(p0, p1), __fadd_rn(p2, p3));
}

// ---------------- mbarrier + bulk copy helpers ----------------
__device__ __forceinline__ void mbar_init(uint32_t mbar, uint32_t cnt) {
    asm volatile("mbarrier.init.shared.b64 [%0], %1;" :: "r"(mbar), "r"(cnt) : "memory");
}
__device__ __forceinline__ void mbar_expect(uint32_t mbar, uint32_t bytes) {
    asm volatile("mbarrier.arrive.expect_tx.shared.b64 _, [%0], %1;"
                 :: "r"(mbar), "r"(bytes) : "memory");
}
__device__ __forceinline__ void mbar_arrive(uint32_t mbar) {
    asm volatile("mbarrier.arrive.shared.b64 _, [%0];" :: "r"(mbar) : "memory");
}
__device__ __forceinline__ void mbar_wait(uint32_t mbar, uint32_t parity) {
    asm volatile(
        "{\n\t.reg .pred P;\n"
        "W_%=:\n\t"
        "mbarrier.try_wait.parity.shared.b64 P, [%0], %1;\n\t"
        "@P bra D_%=;\n\t"
        "bra W_%=;\n"
        "D_%=:\n\t}"
        :: "r"(mbar), "r"(parity) : "memory");
}
__device__ __forceinline__ void bulk_cp(uint32_t dst, const void* src,
                                        uint32_t bytes, uint32_t mbar) {
    asm volatile(
        "cp.async.bulk.shared::cluster.global.mbarrier::complete_tx::bytes "
        "[%0], [%1], %2, [%3];"
        :: "r"(dst), "l"(src), "r"(bytes), "r"(mbar) : "memory");
}

// ---------------- prep: bake stage blobs + zero losses (init merged) --------
__global__ void rvq_prep(const float* __restrict__ in_v, const float* __restrict__ in_g,
                         const float* __restrict__ in_b,
                         const float* __restrict__ out_v, const float* __restrict__ out_g,
                         const float* __restrict__ out_b,
                         const float* __restrict__ cbs, float* __restrict__ out) {
    const int cb  = blockIdx.x;
    const int tid = threadIdx.x;
    float* bA = g_blobA + cb * BLOBA_F;
    float* bB = g_blobB + cb * BLOBB_F;

    if (cb == 0 && tid < 2) out[LOSS_OFF + tid] = 0.0f;   // init losses

    // W_in [8,512]: thread per row; norm = VF4xIC2 FMA accumulators + faddp tree.
    if (tid < DCB) {
        const float* v = in_v + (cb * DCB + tid) * DIN;
        float a[8];
        #pragma unroll
        for (int j = 0; j < 8; j++) a[j] = 0.f;
        for (int k = 0; k < DIN / 8; k++) {
            #pragma unroll
            for (int j = 0; j < 8; j++) {
                float x = v[8 * k + j];
                a[j] = __fmaf_rn(x, x, a[j]);
            }
        }
        float b0 = __fadd_rn(a[0], a[4]);
        float b1 = __fadd_rn(a[1], a[5]);
        float b2 = __fadd_rn(a[2], a[6]);
        float b3 = __fadd_rn(a[3], a[7]);
        float ss = __fadd_rn(__fadd_rn(b0, b1), __fadd_rn(b2, b3));
        float nrm = __fsqrt_rn(ss);
        float g   = in_g[cb * DCB + tid];
        float* dst = bA + tid * 516;
        for (int c = 0; c < DIN; c++) dst[c] = __fdiv_rn(__fmul_rn(g, v[c]), nrm);
        dst[512] = 0.f; dst[513] = 0.f; dst[514] = 0.f; dst[515] = 0.f;
    }
    if (tid < 16) bA[4128 + tid] = (tid < 8) ? in_b[cb * DCB + tid] : 0.f;

    // W_out [512,8]: 8-norm via NEON VF4; TRANSPOSED scalar store [d][c].
    for (int i = tid; i < DIN; i += blockDim.x) {
        const float* v = out_v + (cb * DIN + i) * DCB;
        float vv[8];
        #pragma unroll
        for (int d = 0; d < DCB; d++) vv[d] = v[d];
        float nrm = __fsqrt_rn(ssq8_neon(vv));
        float g   = out_g[cb * DIN + i];
        #pragma unroll
        for (int d = 0; d < DCB; d++)
            bB[10240 + d * 512 + i] = __fdiv_rn(__fmul_rn(g, vv[d]), nrm);
        bB[14336 + i] = out_b[cb * DIN + i];
    }
    // codebook rows: [k][10] = {cb_n[0..7], cn2, 0}; sums via NEON VF4.
    for (int k = tid; k < KCB; k += blockDim.x) {
        const float* v = cbs + (cb * KCB + k) * DCB;
        float vv[8];
        #pragma unroll
        for (int d = 0; d < DCB; d++) vv[d] = v[d];
        float denom = fmaxf(__fsqrt_rn(ssq8_neon(vv)), 1e-12f);
        float cn[8];
        #pragma unroll
        for (int d = 0; d < DCB; d++) {
            cn[d] = __fdiv_rn(vv[d], denom);
            bB[k * 10 + d] = cn[d];
        }
        bB[k * 10 + 8] = ssq8_neon(cn);
        bB[k * 10 + 9] = 0.f;
    }
}

// ---------------- main fused kernel ----------------
// 288 threads: warps 0-7 compute (warp w owns pairs 4w..4w+3, tokens 8w..8w+7);
// warp 8 = producer (weight copies). NO CTA barrier inside the stage loop.
__global__ void __launch_bounds__(288, 1)
rvq_main(const float* __restrict__ z, const float* __restrict__ cbs,
         float* __restrict__ out) {
    extern __shared__ float smF[];
    u64* smU = (u64*)smF;
    uint32_t smB;
    asm("{.reg .u64 t; cvta.to.shared.u64 t, %1; cvt.u32.u64 %0, t;}"
        : "=r"(smB) : "l"(smF));

    const int tid  = threadIdx.x;
    const int lane = tid & 31;
    const int w    = tid >> 5;

    const int tokCTA = blockIdx.x * TOKC;
    const int b     = tokCTA >> 12;
    const int tbase = tokCTA & 4095;

    if (tid == 0) {
        mbar_init(smB + MB_AR0, 1);
        mbar_init(smB + MB_AR1, 1);
        mbar_init(smB + MB_BR, 1);
        mbar_init(smB + MB_AF0, 8);
        mbar_init(smB + MB_AF1, 8);
        mbar_init(smB + MB_BF, 8);
    }

    // ---- load z into R2[p][c] = (z[2p][c], z[2p+1][c]) (first 256 threads) ----
    if (tid < 256) {
        const int p = tid & 31, c0 = tid >> 5;
        const float* zp = z + ((size_t)b << 21) + tbase + 2 * p;
        u64* rb = smU + (size_t)p * 514;
        #pragma unroll 4
        for (int it = 0; it < 64; it++) {
            int c = c0 + 8 * it;
            float2 v = *(const float2*)(zp + ((size_t)c << 12));
            rb[c] = pk2(v.x, v.y);
        }
    }
    __syncthreads();   // the ONLY CTA barrier: mbar init + R2 visible

    if (w == 8) {
        // ================= producer warp =================
        if (lane == 0) {
            mbar_expect(smB + MB_AR0, BLOBA_BYTES);
            bulk_cp(smB + F_A0 * 4u, g_blobA, BLOBA_BYTES, smB + MB_AR0);
            mbar_expect(smB + MB_AR1, BLOBA_BYTES);
            bulk_cp(smB + F_A1 * 4u, g_blobA + BLOBA_F, BLOBA_BYTES, smB + MB_AR1);
            mbar_expect(smB + MB_BR, BLOBB_BYTES);
            bulk_cp(smB + F_B * 4u, g_blobB, BLOBB_BYTES, smB + MB_BR);
            for (int s = 1; s < NCB; s++) {
                // B(s): wait all warps past phase 3 of stage s-1
                mbar_wait(smB + MB_BF, (s - 1) & 1);
                mbar_expect(smB + MB_BR, BLOBB_BYTES);
                bulk_cp(smB + F_B * 4u, g_blobB + s * BLOBB_F, BLOBB_BYTES,
                        smB + MB_BR);
                // A(s+1) into buf (s+1)&1: wait readers of A(s-1) (same buffer)
                if (s + 1 < NCB) {
                    int buf = (s + 1) & 1;
                    int freePhase = ((s + 1) >> 1) - 1;
                    mbar_wait(smB + (buf ? MB_AF1 : MB_AF0), freePhase & 1);
                    mbar_expect(smB + (buf ? MB_AR1 : MB_AR0), BLOBA_BYTES);
                    bulk_cp(smB + (uint32_t)(buf ? F_A1 : F_A0) * 4u,
                            g_blobA + (s + 1) * BLOBA_F, BLOBA_BYTES,
                            smB + (buf ? MB_AR1 : MB_AR0));
                }
            }
        }
        return;   // producer warp done
    }

    // ================= compute warps (0..7) =================
    u64 lossG[4] = {0ULL, 0ULL, 0ULL, 0ULL};

    for (int cb = 0; cb < NCB; cb++) {
        const int buf = cb & 1;
        // wait A(cb) ready: copy index cb>>1 on per-buffer mbar
        mbar_wait(smB + (buf ? MB_AR1 : MB_AR0), (cb >> 1) & 1);
        const float* aCur = smF + (buf ? F_A1 : F_A0);

        // ---- phase 1 (warp-local): sequential ascending FMA chain, dup-on-fly ----
        u64 ze2;
        {
            const int p = tid >> 3, oo = tid & 7;    // p = 4w + (lane>>3)
            const float4* wrow = (const float4*)(aCur + oo * 516);
            const u64* rr = smU + (size_t)p * 514;
            u64 acc = 0ULL;
            #pragma unroll 8
            for (int c4 = 0; c4 < 128; c4++) {
                float4 wv = wrow[c4];
                ulonglong2 r01 = *(const ulonglong2*)(rr + 4 * c4);
                ulonglong2 r23 = *(const ulonglong2*)(rr + 4 * c4 + 2);
                acc = f2(dup2(wv.x), r01.x, acc);
                acc = f2(dup2(wv.y), r01.y, acc);
                acc = f2(dup2(wv.z), r23.x, acc);
                acc = f2(dup2(wv.w), r23.y, acc);
            }
            ze2 = a2(acc, dup2(aCur[4128 + oo]));
        }
        if (lane == 0) mbar_arrive(smB + (buf ? MB_AF1 : MB_AF0));   // A(cb) read done

        // ---- gather ze for this warp's 4 pairs via shuffles ----
        u64 zep[4][8];
        #pragma unroll
        for (int g = 0; g < 4; g++)
            #pragma unroll
            for (int o = 0; o < 8; o++)
                zep[g][o] = __shfl_sync(0xffffffffu, ze2, g * 8 + o);

        // ---- normalization (NEON ordering per token) ----
        u64 zen[4][8], seG[4];
        #pragma unroll
        for (int g = 0; g < 4; g++) {
            float lo[8], hi[8];
            #pragma unroll
            for (int o = 0; o < 8; o++) up2(zep[g][o], lo[o], hi[o]);
            float dl = fmaxf(__fsqrt_rn(ssq8_neon(lo)), 1e-12f);
            float dh = fmaxf(__fsqrt_rn(ssq8_neon(hi)), 1e-12f);
            float nl[8], nh[8];
            #pragma unroll
            for (int o = 0; o < 8; o++) {
                nl[o] = __fdiv_rn(lo[o], dl);
                nh[o] = __fdiv_rn(hi[o], dh);
                zen[g][o] = pk2(nl[o], nh[o]);
            }
            seG[g] = pk2(ssq8_neon(nl), ssq8_neon(nh));
        }
        const u64 NEG2 = dup2(-2.0f);

        mbar_wait(smB + MB_BR, cb & 1);   // B(cb) ready

        // ---- phase 2: dist = (s_e - 2*dot) + c_k ; argmin over 1024 ----
        float bestv[8];
        int   besti[8];
        #pragma unroll
        for (int j = 0; j < 8; j++) { bestv[j] = 3.4e38f; besti[j] = 0; }
        #pragma unroll 2
        for (int kk = 0; kk < 32; kk++) {
            int k = (kk << 5) + lane;
            const float* cbrow = smF + F_CBN + k * 10;
            float2 c01 = *(const float2*)(cbrow);
            float2 c23 = *(const float2*)(cbrow + 2);
            float2 c45 = *(const float2*)(cbrow + 4);
            float2 c67 = *(const float2*)(cbrow + 6);
            float cw[8] = {c01.x, c01.y, c23.x, c23.y, c45.x, c45.y, c67.x, c67.y};
            float cn2k = cbrow[8];
            u64 d0 = 0ULL, d1 = 0ULL, d2 = 0ULL, d3 = 0ULL;
            #pragma unroll
            for (int d = 0; d < 8; d++) {       // sequential ascending FMA (Eigen k=8)
                u64 wc = dup2(cw[d]);
                d0 = f2(wc, zen[0][d], d0);
                d1 = f2(wc, zen[1][d], d1);
                d2 = f2(wc, zen[2][d], d2);
                d3 = f2(wc, zen[3][d], d3);
            }
            u64 c2p = dup2(cn2k);
            u64 s0 = a2(f2(d0, NEG2, seG[0]), c2p);
            u64 s1 = a2(f2(d1, NEG2, seG[1]), c2p);
            u64 s2v = a2(f2(d2, NEG2, seG[2]), c2p);
            u64 s3 = a2(f2(d3, NEG2, seG[3]), c2p);
            float f[8];
            up2(s0, f[0], f[1]); up2(s1, f[2], f[3]);
            up2(s2v, f[4], f[5]); up2(s3, f[6], f[7]);
            #pragma unroll
            for (int j = 0; j < 8; j++)
                if (f[j] < bestv[j]) { bestv[j] = f[j]; besti[j] = k; }
        }
        // cross-lane argmin, first-index tie-break
        #pragma unroll
        for (int j = 0; j < 8; j++) {
            #pragma unroll
            for (int s = 16; s > 0; s >>= 1) {
                float ov = __shfl_xor_sync(0xffffffffu, bestv[j], s);
                int   oi = __shfl_xor_sync(0xffffffffu, besti[j], s);
                if (ov < bestv[j] || (ov == bestv[j] && oi < besti[j])) {
                    bestv[j] = ov; besti[j] = oi;
                }
            }
        }

        // codes output (float), layout [B][NCB][T]; warp tokens = tbase+8w..+7
        {
            float* cOut = out + (((size_t)(b * NCB + cb)) << 12) + tbase + 8 * w;
            int myi = besti[0];
            if (lane == 1) myi = besti[1];
            if (lane == 2) myi = besti[2];
            if (lane == 3) myi = besti[3];
            if (lane == 4) myi = besti[4];
            if (lane == 5) myi = besti[5];
            if (lane == 6) myi = besti[6];
            if (lane == 7) myi = besti[7];
            if (lane < 8) cOut[lane] = (float)myi;
        }

        // losses + straight-through qst (registers; warp-uniform values)
        u64 qst[4][8];
        #pragma unroll
        for (int g = 0; g < 4; g++) {
            const float* qlo = cbs + ((size_t)(cb * KCB + besti[2 * g]) << 3);
            const float* qhi = cbs + ((size_t)(cb * KCB + besti[2 * g + 1]) << 3);
            #pragma unroll
            for (int d = 0; d < 8; d++) {
                u64 zq = pk2(__ldg(qlo + d), __ldg(qhi + d));
                u64 ze = zep[g][d];
                u64 e  = s2(ze, zq);
                lossG[g] = f2(e, e, lossG[g]);
                qst[g][d] = a2(ze, s2(zq, ze));   // z_e + (z_q - z_e)
            }
        }

        // ---- phase 3 (warp-local): residual[own pairs] -= (W_out @ qst + b_out) ----
        {
            #pragma unroll 2
            for (int c16 = 0; c16 < 16; c16++) {
                const int c = lane + 32 * c16;
                u64 Wd[8];
                #pragma unroll
                for (int d = 0; d < 8; d++)
                    Wd[d] = dup2(smF[F_WOUTT + d * 512 + c]);
                const u64 bc = dup2(smF[F_BOUTX + c]);
                #pragma unroll
                for (int g = 0; g < 4; g++) {
                    u64 acc = 0ULL;
                    #pragma unroll
                    for (int d = 0; d < 8; d++) acc = f2(Wd[d], qst[g][d], acc);
                    acc = a2(acc, bc);
                    u64* rp = smU + (4 * w + g) * 514 + c;
                    *rp = s2(*rp, acc);
                }
            }
        }
        if (lane == 0) mbar_arrive(smB + MB_BF);   // B(cb) read done
    }

    // ---- epilogue (warp-local): latent = z - residual_final for own pairs ----
    {
        const int p = 4 * w + (lane >> 3), c0 = lane & 7;
        const float* zp = z + ((size_t)b << 21) + tbase + 2 * p;
        float* lp = out + CODES_N + ((size_t)b << 21) + tbase + 2 * p;
        const u64* rb = smU + (size_t)p * 514;
        #pragma unroll 4
        for (int it = 0; it < 64; it++) {
            int c = c0 + 8 * it;
            float2 zv = *(const float2*)(zp + ((size_t)c << 12));
            float rl, rh;
            up2(rb[c], rl, rh);
            float2 lv;
            lv.x = __fadd_rn(zv.x, -rl);
            lv.y = __fadd_rn(zv.y, -rh);
            *(float2*)(lp + ((size_t)c << 12)) = lv;
        }
    }
    if (lane == 0) {
        float t0, t1, acc = 0.f;
        #pragma unroll
        for (int g = 0; g < 4; g++) {
            up2(lossG[g], t0, t1);
            acc = __fadd_rn(acc, __fadd_rn(t0, t1));
        }
        float wl = __fmul_rn(acc, LOSS_DEN);
        atomicAdd(out + LOSS_OFF, wl);       // closs
        atomicAdd(out + LOSS_OFF + 1, wl);   // bloss (== closs exactly)
    }
}

extern "C" void kernel_launch(void* const* d_in, const int* in_sizes, int n_in,
                              void* d_out, int out_size) {
    const float* z     = (const float*)d_in[0];
    const float* in_v  = (const float*)d_in[1];
    const float* in_g  = (const float*)d_in[2];
    const float* in_b  = (const float*)d_in[3];
    const float* out_v = (const float*)d_in[4];
    const float* out_g = (const float*)d_in[5];
    const float* out_b = (const float*)d_in[6];
    const float* cbs   = (const float*)d_in[7];
    float* out = (float*)d_out;

    cudaFuncSetAttribute(rvq_main, cudaFuncAttributeMaxDynamicSharedMemorySize,
                         F_TOT * sizeof(float));

    rvq_prep<<<NCB, 256>>>(in_v, in_g, in_b, out_v, out_g, out_b, cbs, out);
    rvq_main<<<(BATCH * TLEN) / TOKC, 288, F_TOT * sizeof(float)>>>(z, cbs, out);
}